// round 6
// baseline (speedup 1.0000x reference)
#include <cuda_runtime.h>
#include <math.h>

#define HD    1024
#define SEQ   2048
#define BATCH 16
#define TWOH  2048

// Scratch (no cudaMalloc allowed)
__device__ float g_score[BATCH * SEQ];  // scores, then attn in-place
__device__ float g_rw[TWOH];            // row sums of W1

// tanh with saturation fast path: tanh(x) rounds to +-1.0f in fp32 for |x| >= ~8.7
__device__ __forceinline__ float tanh_acc(float x) {
    float ax = fabsf(x);
    if (ax >= 9.0f) return copysignf(1.0f, x);
    return tanhf(x);
}

// ---------------------------------------------------------------------------
// Kernel 1: rowsum(W1) and zero score buffer.  grid=2048 blocks, 256 thr.
// ---------------------------------------------------------------------------
__global__ void prep_kernel(const float* __restrict__ W1) {
    int i = blockIdx.x;           // row of W1
    int t = threadIdx.x;
    const float* row = W1 + (size_t)i * TWOH;
    float s = 0.f;
    for (int j = t; j < TWOH; j += 256) s += row[j];
    __shared__ float red[8];
    #pragma unroll
    for (int o = 16; o > 0; o >>= 1) s += __shfl_down_sync(0xffffffffu, s, o);
    if ((t & 31) == 0) red[t >> 5] = s;
    __syncthreads();
    if (t < 8) {
        float v = red[t];
        #pragma unroll
        for (int o = 4; o > 0; o >>= 1) v += __shfl_down_sync(0xffu, v, o);
        if (t == 0) g_rw[i] = v;
    }
    // zero score: 2048 blocks * 16 = 32768 entries
    if (t < 16) g_score[i * 16 + t] = 0.f;
}

// ---------------------------------------------------------------------------
// Kernel 2: per-batch GEMM  Z = W1[2048x2048] @ enc_b[2048x1024]  with fused
// epilogue: score[b, s] += sum_i w2[i] * tanh(Z[i, s])   (s < 1024 half)
// Tiling: BM=BN=128, BK=16, 256 threads, 8x8 per thread.
// Register-staged prefetch: LDG(next tile) overlaps compute(current tile).
// grid = (1024/128=8, 2048/128=16, 16)
// ---------------------------------------------------------------------------
__global__ __launch_bounds__(256)
void gemm_kernel(const float* __restrict__ W1,
                 const float* __restrict__ enc,
                 const float* __restrict__ w2) {
    const int b  = blockIdx.z;
    const int i0 = blockIdx.y * 128;
    const int s0 = blockIdx.x * 128;
    const float* E = enc + (size_t)b * SEQ * HD;   // B[k][s] = enc[b, k*HD + s]

    __shared__ float As[16][128];   // As[k][i_local]
    __shared__ float Bs[16][128];   // Bs[k][s_local]
    __shared__ float sscore[128];

    const int tid = threadIdx.x;
    const int tx  = tid & 15;       // -> s group
    const int ty  = tid >> 4;       // -> i group

    // Per-thread load slots (fixed across iterations):
    const int rowA0 = tid >> 2,          kqA0 = tid & 3;
    const int rowA1 = (tid + 256) >> 2,  kqA1 = tid & 3;          // (tid+256)&3 == tid&3
    const int krB0 = tid >> 5,           sqB0 = tid & 31;
    const int krB1 = (tid + 256) >> 5,   sqB1 = tid & 31;

    const float* pA0 = W1 + (size_t)(i0 + rowA0) * TWOH + kqA0 * 4;
    const float* pA1 = W1 + (size_t)(i0 + rowA1) * TWOH + kqA1 * 4;
    const float* pB0 = E  + (size_t)krB0 * HD + s0 + sqB0 * 4;
    const float* pB1 = E  + (size_t)krB1 * HD + s0 + sqB1 * 4;

    float acc[8][8];
    #pragma unroll
    for (int r = 0; r < 8; r++)
        #pragma unroll
        for (int c = 0; c < 8; c++) acc[r][c] = 0.f;

    float4 ra0, ra1, rb0, rb1;

    // --- prologue: load tile kk=0 into regs, stage to smem ---
    ra0 = *(const float4*)(pA0);
    ra1 = *(const float4*)(pA1);
    rb0 = *(const float4*)(pB0);
    rb1 = *(const float4*)(pB1);
    {
        As[kqA0 * 4 + 0][rowA0] = ra0.x; As[kqA0 * 4 + 1][rowA0] = ra0.y;
        As[kqA0 * 4 + 2][rowA0] = ra0.z; As[kqA0 * 4 + 3][rowA0] = ra0.w;
        As[kqA1 * 4 + 0][rowA1] = ra1.x; As[kqA1 * 4 + 1][rowA1] = ra1.y;
        As[kqA1 * 4 + 2][rowA1] = ra1.z; As[kqA1 * 4 + 3][rowA1] = ra1.w;
        *(float4*)&Bs[krB0][sqB0 * 4] = rb0;
        *(float4*)&Bs[krB1][sqB1 * 4] = rb1;
    }
    __syncthreads();

    for (int kk = 16; kk < TWOH; kk += 16) {
        // prefetch next tile into registers (latency hidden by compute below)
        ra0 = *(const float4*)(pA0 + kk);
        ra1 = *(const float4*)(pA1 + kk);
        rb0 = *(const float4*)(pB0 + (size_t)kk * HD);
        rb1 = *(const float4*)(pB1 + (size_t)kk * HD);

        // compute current tile from smem
        #pragma unroll
        for (int k = 0; k < 16; k++) {
            float a[8], bb[8];
            *(float4*)&a[0]  = *(const float4*)&As[k][ty * 8];
            *(float4*)&a[4]  = *(const float4*)&As[k][ty * 8 + 4];
            *(float4*)&bb[0] = *(const float4*)&Bs[k][tx * 8];
            *(float4*)&bb[4] = *(const float4*)&Bs[k][tx * 8 + 4];
            #pragma unroll
            for (int r = 0; r < 8; r++)
                #pragma unroll
                for (int c = 0; c < 8; c++)
                    acc[r][c] = fmaf(a[r], bb[c], acc[r][c]);
        }
        __syncthreads();

        // stage prefetched tile to smem
        As[kqA0 * 4 + 0][rowA0] = ra0.x; As[kqA0 * 4 + 1][rowA0] = ra0.y;
        As[kqA0 * 4 + 2][rowA0] = ra0.z; As[kqA0 * 4 + 3][rowA0] = ra0.w;
        As[kqA1 * 4 + 0][rowA1] = ra1.x; As[kqA1 * 4 + 1][rowA1] = ra1.y;
        As[kqA1 * 4 + 2][rowA1] = ra1.z; As[kqA1 * 4 + 3][rowA1] = ra1.w;
        *(float4*)&Bs[krB0][sqB0 * 4] = rb0;
        *(float4*)&Bs[krB1][sqB1 * 4] = rb1;
        __syncthreads();
    }

    // last tile
    #pragma unroll
    for (int k = 0; k < 16; k++) {
        float a[8], bb[8];
        *(float4*)&a[0]  = *(const float4*)&As[k][ty * 8];
        *(float4*)&a[4]  = *(const float4*)&As[k][ty * 8 + 4];
        *(float4*)&bb[0] = *(const float4*)&Bs[k][tx * 8];
        *(float4*)&bb[4] = *(const float4*)&Bs[k][tx * 8 + 4];
        #pragma unroll
        for (int r = 0; r < 8; r++)
            #pragma unroll
            for (int c = 0; c < 8; c++)
                acc[r][c] = fmaf(a[r], bb[c], acc[r][c]);
    }

    // --- fused epilogue: tanh, *w2, reduce over i, accumulate score ---
    __syncthreads();
    if (tid < 128) sscore[tid] = 0.f;
    __syncthreads();

    float partial[8];
    #pragma unroll
    for (int c = 0; c < 8; c++) partial[c] = 0.f;
    #pragma unroll
    for (int r = 0; r < 8; r++) {
        float wv = w2[i0 + ty * 8 + r];
        #pragma unroll
        for (int c = 0; c < 8; c++)
            partial[c] += wv * tanh_acc(acc[r][c]);
    }
    #pragma unroll
    for (int c = 0; c < 8; c++)
        atomicAdd(&sscore[tx * 8 + c], partial[c]);
    __syncthreads();

    if (tid < 128)
        atomicAdd(&g_score[(size_t)b * SEQ + s0 + tid], sscore[tid]);
}

// ---------------------------------------------------------------------------
// Kernel 3: second-half scores.
// score[b, 1024+t] = sum_i w2[i] * tanh(rw[i] * dec[b, t])
// grid = (1024, 16), 256 threads
// ---------------------------------------------------------------------------
__global__ void dec_score_kernel(const float* __restrict__ dec,
                                 const float* __restrict__ w2) {
    const int t0 = blockIdx.x;
    const int b  = blockIdx.y;
    const float d = dec[b * HD + t0];
    const int tid = threadIdx.x;

    float s = 0.f;
    for (int i = tid; i < TWOH; i += 256)
        s += w2[i] * tanh_acc(g_rw[i] * d);

    __shared__ float red[8];
    #pragma unroll
    for (int o = 16; o > 0; o >>= 1) s += __shfl_down_sync(0xffffffffu, s, o);
    if ((tid & 31) == 0) red[tid >> 5] = s;
    __syncthreads();
    if (tid < 8) {
        float v = red[tid];
        #pragma unroll
        for (int o = 4; o > 0; o >>= 1) v += __shfl_down_sync(0xffu, v, o);
        if (tid == 0) g_score[(size_t)b * SEQ + HD + t0] = v;
    }
}

// ---------------------------------------------------------------------------
// Kernel 4: softmax over s per batch.  grid = 16, 256 threads.
// ---------------------------------------------------------------------------
__global__ void softmax_kernel() {
    const int b = blockIdx.x;
    const int tid = threadIdx.x;
    float* sc = g_score + (size_t)b * SEQ;

    __shared__ float red[8];
    __shared__ float bcast;

    // max
    float m = -1e30f;
    for (int i = tid; i < SEQ; i += 256) m = fmaxf(m, sc[i]);
    #pragma unroll
    for (int o = 16; o > 0; o >>= 1) m = fmaxf(m, __shfl_down_sync(0xffffffffu, m, o));
    if ((tid & 31) == 0) red[tid >> 5] = m;
    __syncthreads();
    if (tid == 0) {
        float v = red[0];
        #pragma unroll
        for (int w = 1; w < 8; w++) v = fmaxf(v, red[w]);
        bcast = v;
    }
    __syncthreads();
    const float M = bcast;

    // exp + sum
    float s = 0.f;
    for (int i = tid; i < SEQ; i += 256) {
        float e = expf(sc[i] - M);
        sc[i] = e;
        s += e;
    }
    __syncthreads();
    #pragma unroll
    for (int o = 16; o > 0; o >>= 1) s += __shfl_down_sync(0xffffffffu, s, o);
    if ((tid & 31) == 0) red[tid >> 5] = s;
    __syncthreads();
    if (tid == 0) {
        float v = 0.f;
        #pragma unroll
        for (int w = 0; w < 8; w++) v += red[w];
        bcast = 1.f / v;
    }
    __syncthreads();
    const float inv = bcast;
    for (int i = tid; i < SEQ; i += 256) sc[i] *= inv;
}

// ---------------------------------------------------------------------------
// Kernel 5: out[b, h] = sum_s attn[b, s] * enc[b, s, h]
// grid = (HD/256=4, 16), 256 threads, one h per thread.
// ---------------------------------------------------------------------------
__global__ void out_kernel(const float* __restrict__ enc, float* __restrict__ out) {
    const int b = blockIdx.y;
    const int h = blockIdx.x * 256 + threadIdx.x;

    __shared__ float sa[SEQ];
    for (int i = threadIdx.x; i < SEQ; i += 256) sa[i] = g_score[(size_t)b * SEQ + i];
    __syncthreads();

    const float* E = enc + (size_t)b * SEQ * HD + h;
    float acc = 0.f;
    #pragma unroll 4
    for (int s = 0; s < SEQ; s++)
        acc = fmaf(sa[s], E[(size_t)s * HD], acc);
    out[b * HD + h] = acc;
}

// ---------------------------------------------------------------------------
extern "C" void kernel_launch(void* const* d_in, const int* in_sizes, int n_in,
                              void* d_out, int out_size) {
    const float *enc = nullptr, *dec = nullptr, *W1 = nullptr, *w2 = nullptr;
    for (int k = 0; k < n_in; k++) {
        switch (in_sizes[k]) {
            case 33554432: enc = (const float*)d_in[k]; break;   // [16,2048,1024]
            case 16384:    dec = (const float*)d_in[k]; break;   // [16,1024]
            case 4194304:  W1  = (const float*)d_in[k]; break;   // [2048,2048]
            case 2048:     w2  = (const float*)d_in[k]; break;   // [1,2048]
        }
    }
    float* out = (float*)d_out;

    prep_kernel<<<TWOH, 256>>>(W1);
    gemm_kernel<<<dim3(HD / 128, TWOH / 128, BATCH), 256>>>(W1, enc, w2);
    dec_score_kernel<<<dim3(HD, BATCH), 256>>>(dec, w2);
    softmax_kernel<<<BATCH, 256>>>();
    out_kernel<<<dim3(HD / 256, BATCH), 256>>>(enc, out);
}

// round 15
// speedup vs baseline: 1.9653x; 1.9653x over previous
#include <cuda_runtime.h>
#include <cuda_fp16.h>
#include <math.h>
#include <stdint.h>

#define HD    1024
#define SEQ   2048
#define BATCH 16
#define TWOH  2048
#define NTOT  (BATCH * HD)     // 16384 combined (b,s) rows

// ---------------------------------------------------------------------------
// Scratch (__device__ globals; cudaMalloc forbidden)
// ---------------------------------------------------------------------------
__device__ float  g_score[BATCH * SEQ];          // scores -> attn in place
__device__ float  g_rw[TWOH];                    // rowsum(W1)
__device__ __half g_w1h[TWOH * TWOH];            // W1 hi  [i][k]
__device__ __half g_w1l[TWOH * TWOH];            // W1 lo  [i][k]
__device__ __half g_eh[NTOT * TWOH];             // enc^T hi [b*1024+s][k]
__device__ __half g_el[NTOT * TWOH];             // enc^T lo [b*1024+s][k]

__device__ __forceinline__ float tanh_acc(float x) {
    float ax = fabsf(x);
    if (ax >= 9.0f) return copysignf(1.0f, x);
    return tanhf(x);
}

__device__ __forceinline__ uint32_t smem_u32(const void* p) {
    uint32_t a;
    asm("{ .reg .u64 t; cvta.to.shared.u64 t, %1; cvt.u32.u64 %0, t; }"
        : "=r"(a) : "l"(p));
    return a;
}

// cp.async (Ampere+, OK on plain sm_103)
__device__ __forceinline__ void cp16(uint32_t s, const void* g) {
    asm volatile("cp.async.ca.shared.global [%0], [%1], 16;\n" :: "r"(s), "l"(g));
}
#define CP_COMMIT() asm volatile("cp.async.commit_group;\n" ::: "memory")
#define CP_WAIT1()  asm volatile("cp.async.wait_group 1;\n" ::: "memory")
#define CP_WAIT0()  asm volatile("cp.async.wait_group 0;\n" ::: "memory")

__device__ __forceinline__ void ldm_x4(uint32_t& r0, uint32_t& r1, uint32_t& r2,
                                       uint32_t& r3, uint32_t addr) {
    asm volatile("ldmatrix.sync.aligned.m8n8.x4.shared.b16 {%0,%1,%2,%3}, [%4];"
                 : "=r"(r0), "=r"(r1), "=r"(r2), "=r"(r3) : "r"(addr));
}
// B operand: smem stores each n-row with contiguous k (col-major B for row.col
// mma) -> NON-trans ldmatrix yields the b-fragment directly.
__device__ __forceinline__ void ldm_x2(uint32_t& r0, uint32_t& r1, uint32_t addr) {
    asm volatile("ldmatrix.sync.aligned.m8n8.x2.shared.b16 {%0,%1}, [%2];"
                 : "=r"(r0), "=r"(r1) : "r"(addr));
}
__device__ __forceinline__ void mma16816(float* c, uint32_t a0, uint32_t a1,
                                         uint32_t a2, uint32_t a3,
                                         uint32_t b0, uint32_t b1) {
    asm volatile("mma.sync.aligned.m16n8k16.row.col.f32.f16.f16.f32 "
                 "{%0,%1,%2,%3}, {%4,%5,%6,%7}, {%8,%9}, {%0,%1,%2,%3};"
                 : "+f"(c[0]), "+f"(c[1]), "+f"(c[2]), "+f"(c[3])
                 : "r"(a0), "r"(a1), "r"(a2), "r"(a3), "r"(b0), "r"(b1));
}

// ---------------------------------------------------------------------------
// Kernel 1: rowsum(W1) + zero score.
// ---------------------------------------------------------------------------
__global__ void prep_kernel(const float* __restrict__ W1) {
    int i = blockIdx.x;
    int t = threadIdx.x;
    const float* row = W1 + (size_t)i * TWOH;
    float s = 0.f;
    for (int j = t; j < TWOH; j += 256) s += row[j];
    __shared__ float red[8];
    #pragma unroll
    for (int o = 16; o > 0; o >>= 1) s += __shfl_down_sync(0xffffffffu, s, o);
    if ((t & 31) == 0) red[t >> 5] = s;
    __syncthreads();
    if (t < 8) {
        float v = red[t];
        #pragma unroll
        for (int o = 4; o > 0; o >>= 1) v += __shfl_down_sync(0xffu, v, o);
        if (t == 0) g_rw[i] = v;
    }
    if (t < 16) g_score[i * 16 + t] = 0.f;
}

// ---------------------------------------------------------------------------
// Kernel 2a: split W1 fp32 -> (hi, lo) fp16, same [i][k] layout.
// ---------------------------------------------------------------------------
__global__ void conv_w1_kernel(const float* __restrict__ W1) {
    size_t base = ((size_t)blockIdx.x * 256 + threadIdx.x) * 8;
    #pragma unroll
    for (int j = 0; j < 8; j++) {
        float v = W1[base + j];
        __half h = __float2half_rn(v);
        __half l = __float2half_rn(v - __half2float(h));
        g_w1h[base + j] = h;
        g_w1l[base + j] = l;
    }
}

// ---------------------------------------------------------------------------
// Kernel 2b: split + transpose enc:  g_e*[b*1024+s][k] = enc[b][k][s]
// ---------------------------------------------------------------------------
__global__ void conv_enc_kernel(const float* __restrict__ enc) {
    __shared__ float T[64][65];
    const int s0 = blockIdx.x * 64;
    const int k0 = blockIdx.y * 64;
    const int b  = blockIdx.z;
    const float* E = enc + (size_t)b * TWOH * HD;

    #pragma unroll
    for (int j = 0; j < 16; j++) {
        int idx = threadIdx.x + j * 256;
        int kr = idx >> 6, sc = idx & 63;
        T[kr][sc] = E[(size_t)(k0 + kr) * HD + s0 + sc];
    }
    __syncthreads();
    #pragma unroll
    for (int j = 0; j < 16; j++) {
        int idx = threadIdx.x + j * 256;
        int sr = idx >> 6, kc = idx & 63;
        float v = T[kc][sr];
        __half h = __float2half_rn(v);
        __half l = __float2half_rn(v - __half2float(h));
        size_t o = (size_t)(b * HD + s0 + sr) * TWOH + k0 + kc;
        g_eh[o] = h;
        g_el[o] = l;
    }
}

// ---------------------------------------------------------------------------
// Kernel 3: mma.sync fp16-split GEMM + fused tanh/w2/reduce epilogue.
// Z[i, bs] = W1[i,:] . encT[bs,:]  via 3 splits (hh, hl, lh), fp32 accum.
// CTA 128x128, BK=32, 8 warps (4m x 2n), warp tile 32x64 (2 m16 x 8 n8).
// cp.async double-buffered smem, padded 80B rows.
// grid (16 i-tiles, 128 bs-tiles), 256 threads.
// ---------------------------------------------------------------------------
#define BK        32
#define ROWP      40                       // padded row in halfs (80 B)
#define TILE_BY   (128 * ROWP * 2)         // 10240 B per operand tile
#define BUF_BY    (4 * TILE_BY)            // Ah, Al, Bh, Bl = 40960 B
#define OFF_SS    (2 * BUF_BY)             // sscore after 2 buffers
#define GEMM_SMEM (OFF_SS + 512)

__device__ __forceinline__ void prefetch_chunk(
    uint32_t smem_base, int buf, int c, int tid,
    const __half* Ah, const __half* Al, const __half* Bh, const __half* Bl) {
    const __half* srcs[4] = { Ah, Al, Bh, Bl };
    #pragma unroll
    for (int op = 0; op < 4; op++) {
        #pragma unroll
        for (int l = 0; l < 2; l++) {
            int slot = tid + l * 256;
            int row = slot >> 2, q = slot & 3;
            const void* g = srcs[op] + (size_t)row * TWOH + c * BK + q * 8;
            uint32_t s = smem_base + buf * BUF_BY + op * TILE_BY + row * 80 + q * 16;
            cp16(s, g);
        }
    }
}

__global__ __launch_bounds__(256)
void gemm16_kernel(const float* __restrict__ w2) {
    extern __shared__ char smem[];
    const uint32_t smem_base = smem_u32(smem);
    const int tid  = threadIdx.x;
    const int wid  = tid >> 5;
    const int lane = tid & 31;
    const int i0   = blockIdx.x * 128;
    const int bs0  = blockIdx.y * 128;
    const int warp_m = (wid & 3) * 32;
    const int warp_n = (wid >> 2) * 64;

    float* sscore = (float*)(smem + OFF_SS);
    if (tid < 128) sscore[tid] = 0.f;

    const __half* Ah = g_w1h + (size_t)i0 * TWOH;
    const __half* Al = g_w1l + (size_t)i0 * TWOH;
    const __half* Bh = g_eh  + (size_t)bs0 * TWOH;
    const __half* Bl = g_el  + (size_t)bs0 * TWOH;

    float acc[2][8][4];
    #pragma unroll
    for (int mt = 0; mt < 2; mt++)
        #pragma unroll
        for (int nt = 0; nt < 8; nt++)
            #pragma unroll
            for (int j = 0; j < 4; j++) acc[mt][nt][j] = 0.f;

    // ldmatrix lane addressing (byte offsets within a tile)
    const int a_row = lane & 15;                 // + warp_m + mt*16
    const int a_kof = (lane >> 4) * 16;          // bytes: 8 halfs
    const int b_row = lane & 7;                  // + warp_n + nt*8
    const int b_kof = ((lane >> 3) & 1) * 16;

    prefetch_chunk(smem_base, 0, 0, tid, Ah, Al, Bh, Bl);
    CP_COMMIT();

    const int NCH = TWOH / BK;                   // 64
    for (int c = 0; c < NCH; c++) {
        const int buf = c & 1;
        if (c + 1 < NCH) {
            prefetch_chunk(smem_base, (c + 1) & 1, c + 1, tid, Ah, Al, Bh, Bl);
            CP_COMMIT();
            CP_WAIT1();
        } else {
            CP_WAIT0();
        }
        __syncthreads();

        const uint32_t bb = smem_base + buf * BUF_BY;
        #pragma unroll
        for (int ks = 0; ks < 2; ks++) {
            const int kby = ks * 32;             // bytes: 16 halfs
            uint32_t ah[2][4], al[2][4], bh[8][2], bl[8][2];
            #pragma unroll
            for (int mt = 0; mt < 2; mt++) {
                uint32_t ra = bb + 0 * TILE_BY + (warp_m + mt * 16 + a_row) * 80 + kby + a_kof;
                ldm_x4(ah[mt][0], ah[mt][1], ah[mt][2], ah[mt][3], ra);
                uint32_t rl = bb + 1 * TILE_BY + (warp_m + mt * 16 + a_row) * 80 + kby + a_kof;
                ldm_x4(al[mt][0], al[mt][1], al[mt][2], al[mt][3], rl);
            }
            #pragma unroll
            for (int nt = 0; nt < 8; nt++) {
                uint32_t rb = bb + 2 * TILE_BY + (warp_n + nt * 8 + b_row) * 80 + kby + b_kof;
                ldm_x2(bh[nt][0], bh[nt][1], rb);
                uint32_t rc = bb + 3 * TILE_BY + (warp_n + nt * 8 + b_row) * 80 + kby + b_kof;
                ldm_x2(bl[nt][0], bl[nt][1], rc);
            }
            #pragma unroll
            for (int mt = 0; mt < 2; mt++)
                #pragma unroll
                for (int nt = 0; nt < 8; nt++) {
                    mma16816(acc[mt][nt], ah[mt][0], ah[mt][1], ah[mt][2], ah[mt][3],
                             bh[nt][0], bh[nt][1]);
                    mma16816(acc[mt][nt], ah[mt][0], ah[mt][1], ah[mt][2], ah[mt][3],
                             bl[nt][0], bl[nt][1]);
                    mma16816(acc[mt][nt], al[mt][0], al[mt][1], al[mt][2], al[mt][3],
                             bh[nt][0], bh[nt][1]);
                }
        }
        __syncthreads();
    }

    // ---- epilogue: score[s] += sum_i w2[i] * tanh(Z[i][s]) ----
    // acc mapping: c0 (row = lane/4, col = 2*(lane%4)), c1 col+1, c2/c3 row+8.
    float wv[2][2];
    #pragma unroll
    for (int mt = 0; mt < 2; mt++) {
        int r = i0 + warp_m + mt * 16 + (lane >> 2);
        wv[mt][0] = w2[r];
        wv[mt][1] = w2[r + 8];
    }
    #pragma unroll
    for (int nt = 0; nt < 8; nt++) {
        #pragma unroll
        for (int j = 0; j < 2; j++) {
            float part = 0.f;
            #pragma unroll
            for (int mt = 0; mt < 2; mt++) {
                part += wv[mt][0] * tanh_acc(acc[mt][nt][j]);
                part += wv[mt][1] * tanh_acc(acc[mt][nt][2 + j]);
            }
            // reduce over the 8 lanes sharing this column (stride 4)
            part += __shfl_xor_sync(0xffffffffu, part, 4);
            part += __shfl_xor_sync(0xffffffffu, part, 8);
            part += __shfl_xor_sync(0xffffffffu, part, 16);
            if (lane < 4) {
                int col = warp_n + nt * 8 + 2 * lane + j;
                atomicAdd(&sscore[col], part);
            }
        }
    }
    __syncthreads();

    if (tid < 128) {
        int bs = bs0 + tid;
        int b = bs >> 10, s = bs & 1023;
        atomicAdd(&g_score[(size_t)b * SEQ + s], sscore[tid]);
    }
}

// ---------------------------------------------------------------------------
// Kernel 4: second-half scores. score[b,1024+t] = sum_i w2[i]*tanh(rw[i]*dec[b,t])
// ---------------------------------------------------------------------------
__global__ void dec_score_kernel(const float* __restrict__ dec,
                                 const float* __restrict__ w2) {
    const int t0 = blockIdx.x;
    const int b  = blockIdx.y;
    const float d = dec[b * HD + t0];
    const int tid = threadIdx.x;

    float s = 0.f;
    for (int i = tid; i < TWOH; i += 256)
        s += w2[i] * tanh_acc(g_rw[i] * d);

    __shared__ float red[8];
    #pragma unroll
    for (int o = 16; o > 0; o >>= 1) s += __shfl_down_sync(0xffffffffu, s, o);
    if ((tid & 31) == 0) red[tid >> 5] = s;
    __syncthreads();
    if (tid < 8) {
        float v = red[tid];
        #pragma unroll
        for (int o = 4; o > 0; o >>= 1) v += __shfl_down_sync(0xffu, v, o);
        if (tid == 0) g_score[(size_t)b * SEQ + HD + t0] = v;
    }
}

// ---------------------------------------------------------------------------
// Kernel 5: softmax over s per batch.
// ---------------------------------------------------------------------------
__global__ void softmax_kernel() {
    const int b = blockIdx.x;
    const int tid = threadIdx.x;
    float* sc = g_score + (size_t)b * SEQ;

    __shared__ float red[8];
    __shared__ float bcast;

    float m = -1e30f;
    for (int i = tid; i < SEQ; i += 256) m = fmaxf(m, sc[i]);
    #pragma unroll
    for (int o = 16; o > 0; o >>= 1) m = fmaxf(m, __shfl_down_sync(0xffffffffu, m, o));
    if ((tid & 31) == 0) red[tid >> 5] = m;
    __syncthreads();
    if (tid == 0) {
        float v = red[0];
        #pragma unroll
        for (int w = 1; w < 8; w++) v = fmaxf(v, red[w]);
        bcast = v;
    }
    __syncthreads();
    const float M = bcast;

    float s = 0.f;
    for (int i = tid; i < SEQ; i += 256) {
        float e = expf(sc[i] - M);
        sc[i] = e;
        s += e;
    }
    __syncthreads();
    #pragma unroll
    for (int o = 16; o > 0; o >>= 1) s += __shfl_down_sync(0xffffffffu, s, o);
    if ((tid & 31) == 0) red[tid >> 5] = s;
    __syncthreads();
    if (tid == 0) {
        float v = 0.f;
        #pragma unroll
        for (int w = 0; w < 8; w++) v += red[w];
        bcast = 1.f / v;
    }
    __syncthreads();
    const float inv = bcast;
    for (int i = tid; i < SEQ; i += 256) sc[i] *= inv;
}

// ---------------------------------------------------------------------------
// Kernel 6: out[b, h] = sum_s attn[b, s] * enc[b, s, h]
// ---------------------------------------------------------------------------
__global__ void out_kernel(const float* __restrict__ enc, float* __restrict__ out) {
    const int b = blockIdx.y;
    const int h = blockIdx.x * 256 + threadIdx.x;

    __shared__ float sa[SEQ];
    for (int i = threadIdx.x; i < SEQ; i += 256) sa[i] = g_score[(size_t)b * SEQ + i];
    __syncthreads();

    const float* E = enc + (size_t)b * SEQ * HD + h;
    float acc = 0.f;
    #pragma unroll 4
    for (int s = 0; s < SEQ; s++)
        acc = fmaf(sa[s], E[(size_t)s * HD], acc);
    out[b * HD + h] = acc;
}

// ---------------------------------------------------------------------------
extern "C" void kernel_launch(void* const* d_in, const int* in_sizes, int n_in,
                              void* d_out, int out_size) {
    const float *enc = nullptr, *dec = nullptr, *W1 = nullptr, *w2 = nullptr;
    for (int k = 0; k < n_in; k++) {
        switch (in_sizes[k]) {
            case 33554432: enc = (const float*)d_in[k]; break;   // [16,2048,1024]
            case 16384:    dec = (const float*)d_in[k]; break;   // [16,1024]
            case 4194304:  W1  = (const float*)d_in[k]; break;   // [2048,2048]
            case 2048:     w2  = (const float*)d_in[k]; break;   // [1,2048]
        }
    }
    float* out = (float*)d_out;

    cudaFuncSetAttribute(gemm16_kernel,
                         cudaFuncAttributeMaxDynamicSharedMemorySize, GEMM_SMEM);

    prep_kernel<<<TWOH, 256>>>(W1);
    conv_w1_kernel<<<TWOH, 256>>>(W1);
    conv_enc_kernel<<<dim3(HD / 64, TWOH / 64, BATCH), 256>>>(enc);
    gemm16_kernel<<<dim3(TWOH / 128, NTOT / 128), 256, GEMM_SMEM>>>(w2);
    dec_score_kernel<<<dim3(HD, BATCH), 256>>>(dec, w2);
    softmax_kernel<<<BATCH, 256>>>();
    out_kernel<<<dim3(HD / 256, BATCH), 256>>>(enc, out);
}